// round 2
// baseline (speedup 1.0000x reference)
#include <cuda_runtime.h>
#include <cuda_bf16.h>

// Problem: out[row[e]] += values[e] * x[col[e]],  row sorted ascending.
// E = 1.6M, N = 100k, D = 64.
//
// Strategy:
//   Kernel 1: row_ptr[r] = lower_bound(row, E, r) via per-thread binary search.
//             row is sorted, so CSR offsets are recoverable in ~21 steps/row.
//   Kernel 2: one warp per row. lane l owns features [2l, 2l+1] (float2).
//             Registers accumulate over the row's edges; single plain store.
//             No atomics, no zero-init pass (every row stored exactly once).

#define N_NODES 100000
#define D_FEAT 64

__device__ int g_row_ptr[N_NODES + 1];

__global__ void build_row_ptr_kernel(const int* __restrict__ row, int n_edges, int n_nodes) {
    int r = blockIdx.x * blockDim.x + threadIdx.x;
    if (r > n_nodes) return;
    if (r == n_nodes) { g_row_ptr[r] = n_edges; return; }
    // lower_bound: first index i with row[i] >= r
    int lo = 0, hi = n_edges;
    while (lo < hi) {
        int mid = (lo + hi) >> 1;
        if (row[mid] < r) lo = mid + 1;
        else hi = mid;
    }
    g_row_ptr[r] = lo;
}

__global__ void __launch_bounds__(256) spmm_row_warp_kernel(
    const int* __restrict__ col,
    const float* __restrict__ val,
    const float* __restrict__ x,
    float* __restrict__ out,
    int n_nodes)
{
    int r = (blockIdx.x * blockDim.x + threadIdx.x) >> 5;
    if (r >= n_nodes) return;
    int lane = threadIdx.x & 31;

    int s = g_row_ptr[r];
    int e = g_row_ptr[r + 1];

    const float2* __restrict__ x2 = (const float2*)x;
    float2 acc = make_float2(0.f, 0.f);

    #pragma unroll 4
    for (int i = s; i < e; ++i) {
        int   c = __ldg(&col[i]);   // uniform across warp -> L1 broadcast
        float v = __ldg(&val[i]);
        float2 xv = __ldg(&x2[(long)c * (D_FEAT / 2) + lane]);  // coalesced 256B gather, L2-resident
        acc.x = fmaf(v, xv.x, acc.x);
        acc.y = fmaf(v, xv.y, acc.y);
    }

    ((float2*)out)[(long)r * (D_FEAT / 2) + lane] = acc;
}

extern "C" void kernel_launch(void* const* d_in, const int* in_sizes, int n_in,
                              void* d_out, int out_size) {
    const int*   row = (const int*)d_in[0];
    const int*   col = (const int*)d_in[1];
    const float* val = (const float*)d_in[2];
    const float* x   = (const float*)d_in[3];
    float*       out = (float*)d_out;

    int n_edges = in_sizes[0];
    int n_nodes = in_sizes[3] / D_FEAT;

    {
        int threads = 256;
        int blocks = (n_nodes + 1 + threads - 1) / threads;
        build_row_ptr_kernel<<<blocks, threads>>>(row, n_edges, n_nodes);
    }
    {
        int threads = 256;                 // 8 warps/block
        long warps = n_nodes;
        int blocks = (int)((warps * 32 + threads - 1) / threads);
        spmm_row_warp_kernel<<<blocks, threads>>>(col, val, x, out, n_nodes);
    }
}